// round 2
// baseline (speedup 1.0000x reference)
#include <cuda_runtime.h>
#include <math.h>

// ---------------- static scratch (no allocations allowed) ----------------
#define TOT_CH 1472
#define GIDX_TOTAL 28108800ULL

__device__ unsigned char g_gidx[GIDX_TOTAL];          // per-pixel gidx, per channel
__device__ unsigned int  g_chmin[TOT_CH], g_chmax[TOT_CH];   // ordered-key encoded
__device__ int           g_cbin[TOT_CH][6];            // hist bins (bin_idx)
__device__ int           g_cg[TOT_CH][6];              // gidx counts
__device__ int           g_gb[TOT_CH];                 // gidx at border (from pixel 0,0)
__device__ float         g_ptab[TOT_CH][6];            // pondered-map value per gidx
__device__ float         g_pborder[TOT_CH];            // pondered value at border (c>=1)
__device__ float         g_proc[306900];               // per-layer proc images (concat)
__device__ unsigned int  g_procmin[5], g_procmax[5];
__device__ float         g_resized[5 * 57600];
__device__ unsigned int  g_rmin[5], g_rmax[5];
__device__ float         g_rsum[5];

// ordered-key encoding so atomicMin/Max on unsigned == float min/max
__device__ __forceinline__ unsigned fkey(float f) {
    unsigned u = __float_as_uint(f);
    return (u & 0x80000000u) ? ~u : (u | 0x80000000u);
}
__device__ __forceinline__ float funkey(unsigned u) {
    return (u & 0x80000000u) ? __uint_as_float(u & 0x7fffffffu) : __uint_as_float(~u);
}

__device__ __forceinline__ float wrMin(float v) {
    #pragma unroll
    for (int o = 16; o; o >>= 1) v = fminf(v, __shfl_xor_sync(0xffffffffu, v, o));
    return v;
}
__device__ __forceinline__ float wrMax(float v) {
    #pragma unroll
    for (int o = 16; o; o >>= 1) v = fmaxf(v, __shfl_xor_sync(0xffffffffu, v, o));
    return v;
}
__device__ __forceinline__ float wrSum(float v) {
    #pragma unroll
    for (int o = 16; o; o >>= 1) v += __shfl_xor_sync(0xffffffffu, v, o);
    return v;
}
__device__ __forceinline__ int wrSumI(int v) {
    #pragma unroll
    for (int o = 16; o; o >>= 1) v += __shfl_xor_sync(0xffffffffu, v, o);
    return v;
}

// block reductions (blockDim.x == 256 everywhere these are used)
__device__ void blockMinMax(float& mn, float& mx) {
    __shared__ float smn[8], smx[8];
    int lane = threadIdx.x & 31, w = threadIdx.x >> 5;
    mn = wrMin(mn); mx = wrMax(mx);
    if (lane == 0) { smn[w] = mn; smx[w] = mx; }
    __syncthreads();
    if (threadIdx.x < 8) { mn = smn[threadIdx.x]; mx = smx[threadIdx.x]; }
    else { mn = INFINITY; mx = -INFINITY; }
    if (w == 0) { mn = wrMin(mn); mx = wrMax(mx); }
}
__device__ void blockMinMaxSum(float& mn, float& mx, float& sm) {
    __shared__ float smn[8], smx[8], ssm[8];
    int lane = threadIdx.x & 31, w = threadIdx.x >> 5;
    mn = wrMin(mn); mx = wrMax(mx); sm = wrSum(sm);
    if (lane == 0) { smn[w] = mn; smx[w] = mx; ssm[w] = sm; }
    __syncthreads();
    if (threadIdx.x < 8) { mn = smn[threadIdx.x]; mx = smx[threadIdx.x]; sm = ssm[threadIdx.x]; }
    else { mn = INFINITY; mx = -INFINITY; sm = 0.f; }
    if (w == 0) { mn = wrMin(mn); mx = wrMax(mx); sm = wrSum(sm); }
}

// ---------------- kernels ----------------

__global__ void k_init() {
    int i = blockIdx.x * blockDim.x + threadIdx.x;
    if (i < TOT_CH) { g_chmin[i] = 0xFFFFFFFFu; g_chmax[i] = 0u; }
    if (i < TOT_CH * 6) { ((int*)g_cbin)[i] = 0; ((int*)g_cg)[i] = 0; }
    if (i < 5) {
        g_procmin[i] = 0xFFFFFFFFu; g_procmax[i] = 0u;
        g_rmin[i]    = 0xFFFFFFFFu; g_rmax[i]    = 0u;
        g_rsum[i]    = 0.f;
    }
}

// per-channel min/max over zero-bordered channel. grid = (splits, C)
__global__ void k_minmax(const float* __restrict__ in, int H, int chanBase, int splits) {
    int c = blockIdx.y;
    int W = H, HW = H * W;
    const float* ch = in + (size_t)c * HW;
    int chunk = (HW + splits - 1) / splits;
    int lo = blockIdx.x * chunk, hi = min(HW, lo + chunk);
    float vmn = INFINITY, vmx = -INFINITY;
    for (int p = lo + threadIdx.x; p < hi; p += blockDim.x) {
        int y = p / W, x = p - y * W;
        float val = (y == 0 || x == 0 || y == H - 1 || x == W - 1) ? 0.f : ch[p];
        vmn = fminf(vmn, val); vmx = fmaxf(vmx, val);
    }
    blockMinMax(vmn, vmx);
    if (threadIdx.x == 0) {
        atomicMin(&g_chmin[chanBase + c], fkey(vmn));
        atomicMax(&g_chmax[chanBase + c], fkey(vmx));
    }
}

// per-channel histograms (bin_idx + gidx) and gidx byte store. grid = (splits, C)
__global__ void k_hist(const float* __restrict__ in, int H, int chanBase,
                       unsigned long long gOff, int splits) {
    int c = blockIdx.y;
    int W = H, HW = H * W;
    const float* ch = in + (size_t)c * HW;
    unsigned char* gout = g_gidx + gOff + (size_t)c * HW;
    int gch = chanBase + c;
    float mn = funkey(g_chmin[gch]);
    float mx = funkey(g_chmax[gch]);
    float rng = mx - mn;
    const float c6 = 256.0f / 6.0f;

    int cbL[6] = {0, 0, 0, 0, 0, 0};
    int cgL[6] = {0, 0, 0, 0, 0, 0};

    int chunk = (HW + splits - 1) / splits;
    int lo = blockIdx.x * chunk, hi = min(HW, lo + chunk);
    for (int p = lo + threadIdx.x; p < hi; p += blockDim.x) {
        int y = p / W, x = p - y * W;
        float val = (y == 0 || x == 0 || y == H - 1 || x == W - 1) ? 0.f : ch[p];
        float v = (rng == 0.f) ? 0.f
                               : __fmul_rn(__fdiv_rn(__fsub_rn(val, mn), rng), 256.0f);
        int b = (int)floorf(__fdiv_rn(v, c6));
        b = max(0, min(5, b));
        int g = (int)truncf(__fsub_rn(__fmul_rn(v, 6.0f), 1.0f));
        g = max(0, min(5, g));
        #pragma unroll
        for (int k = 0; k < 6; k++) { cbL[k] += (b == k); cgL[k] += (g == k); }
        gout[p] = (unsigned char)g;
        if (p == 0) g_gb[gch] = g;
    }
    int lane = threadIdx.x & 31;
    #pragma unroll
    for (int k = 0; k < 6; k++) {
        int vb = wrSumI(cbL[k]);
        int vg = wrSumI(cgL[k]);
        if (lane == 0) {
            if (vb) atomicAdd(&g_cbin[gch][k], vb);
            if (vg) atomicAdd(&g_cg[gch][k], vg);
        }
    }
}

// per-channel table math: rarity table -> pondered-map table. one thread per channel.
__global__ void k_tables() {
    int ch = blockIdx.x * blockDim.x + threadIdx.x;
    if (ch >= TOT_CH) return;
    const int cb[6] = {0, 64, 192, 448, 960, 1472};
    const int Hs[5] = {480, 240, 120, 60, 30};
    int layer = 0;
    #pragma unroll
    for (int l = 1; l < 5; l++) if (ch >= cb[l]) layer = l;
    int cIn = ch - cb[layer];
    int H = Hs[layer], HW = H * H, nb = 4 * H - 4;

    float hv[6]; int cg[6];
    #pragma unroll
    for (int b = 0; b < 6; b++) {
        hv[b] = -logf((float)g_cbin[ch][b] / (float)HW + 1e-4f);
        cg[b] = g_cg[ch][b];
    }
    // dst = normalize(hist[gidx], 0, 1)
    float dmn = INFINITY, dmx = -INFINITY;
    #pragma unroll
    for (int g = 0; g < 6; g++) if (cg[g] > 0) { dmn = fminf(dmn, hv[g]); dmx = fmaxf(dmx, hv[g]); }
    float drng = dmx - dmn;
    float dst[6];
    #pragma unroll
    for (int g = 0; g < 6; g++) dst[g] = (drng == 0.f) ? 0.f : (hv[g] - dmn) / drng;
    float meanD = 0.f;
    #pragma unroll
    for (int g = 0; g < 6; g++) meanD += (float)cg[g] * dst[g];
    meanD /= (float)HW;
    float maxD = -INFINITY;
    #pragma unroll
    for (int g = 0; g < 6; g++) if (cg[g] > 0) maxD = fmaxf(maxD, dst[g]);
    // _ponder(dst): normalize(dst)==dst exactly (present min/max are exactly 0/1)
    float wr = (maxD - meanD); wr *= wr;
    float rt[6];
    #pragma unroll
    for (int g = 0; g < 6; g++) rt[g] = dst[g] * wr;

    // maps stats: c==0 keeps border (value rt[gb]); c>=1 border zeroed
    int gb = g_gb[ch];
    float mmn, mmx, msum = 0.f;
    if (cIn == 0) {
        mmn = INFINITY; mmx = -INFINITY;
        #pragma unroll
        for (int g = 0; g < 6; g++) if (cg[g] > 0) {
            mmn = fminf(mmn, rt[g]); mmx = fmaxf(mmx, rt[g]); msum += (float)cg[g] * rt[g];
        }
    } else {
        mmn = 0.f; mmx = 0.f;  // border zeros always present
        #pragma unroll
        for (int g = 0; g < 6; g++) {
            int ci = cg[g] - ((g == gb) ? nb : 0);
            if (ci > 0) { mmn = fminf(mmn, rt[g]); mmx = fmaxf(mmx, rt[g]); msum += (float)ci * rt[g]; }
        }
    }
    float mrng = mmx - mmn;
    float wp = mmx - msum / (float)HW; wp *= wp;
    #pragma unroll
    for (int g = 0; g < 6; g++)
        g_ptab[ch][g] = (mrng == 0.f) ? 0.f : ((rt[g] - mmn) / mrng) * wp;
    g_pborder[ch] = (cIn == 0) ? 0.f
                               : ((mrng == 0.f) ? 0.f : ((0.f - mmn) / mrng) * wp);
}

// proc(p) = sum_c ptab_c[gidx_c(p)]; also layer min/max
__global__ void k_proc(int C, int H, int chanBase, unsigned long long gOff,
                       int pOff, int layer) {
    __shared__ float s_ptab[512 * 6];
    __shared__ float s_pb[512];
    int tid = threadIdx.x;
    for (int i = tid; i < C * 6; i += blockDim.x)
        s_ptab[i] = g_ptab[chanBase + i / 6][i % 6];
    for (int i = tid; i < C; i += blockDim.x)
        s_pb[i] = g_pborder[chanBase + i];
    __syncthreads();

    int W = H, HW = H * W;
    int p = blockIdx.x * blockDim.x + tid;
    float mn = INFINITY, mx = -INFINITY;
    if (p < HW) {
        int y = p / W, x = p - y * W;
        bool border = (y == 0 || x == 0 || y == H - 1 || x == W - 1);
        const unsigned char* gp = g_gidx + gOff + p;
        float s = 0.f;
        if (!border) {
            for (int c = 0; c < C; c++) s += s_ptab[c * 6 + gp[(size_t)c * HW]];
        } else {
            s = s_ptab[gp[0]];          // channel 0 keeps its border value
            for (int c = 1; c < C; c++) s += s_pb[c];
        }
        g_proc[pOff + p] = s;
        mn = s; mx = s;
    }
    blockMinMax(mn, mx);
    if (tid == 0) {
        atomicMin(&g_procmin[layer], fkey(mn));
        atomicMax(&g_procmax[layer], fkey(mx));
    }
}

// jax.image.resize (linear, antialias=True) of thresholded normalized proc -> 240x240
__global__ void k_resize(int H, int pOff, int layer) {
    int o = blockIdx.x * blockDim.x + threadIdx.x;  // 0..57599
    int W = H;
    float pmn = funkey(g_procmin[layer]);
    float pmx = funkey(g_procmax[layer]);
    float prng = pmx - pmn;
    int oy = o / 240, ox = o - oy * 240;
    float inv = (float)H / 240.0f;
    float ks = fmaxf(inv, 1.0f);
    float fy = ((float)oy + 0.5f) * inv - 0.5f;
    float fx = ((float)ox + 0.5f) * inv - 0.5f;
    int ylo = max(0, (int)ceilf(fy - ks)), yhi = min(H - 1, (int)floorf(fy + ks));
    int xlo = max(0, (int)ceilf(fx - ks)), xhi = min(W - 1, (int)floorf(fx + ks));
    float wx[8]; float wxs = 0.f;
    for (int j = xlo; j <= xhi; j++) {
        float w = fmaxf(0.f, 1.0f - fabsf(fx - (float)j) / ks);
        wx[j - xlo] = w; wxs += w;
    }
    const float* pr = g_proc + pOff;
    float acc = 0.f, wys = 0.f;
    for (int j = ylo; j <= yhi; j++) {
        float wy = fmaxf(0.f, 1.0f - fabsf(fy - (float)j) / ks);
        wys += wy;
        if (wy != 0.f) {
            float rowacc = 0.f;
            for (int i = xlo; i <= xhi; i++) {
                float v = pr[j * W + i];
                float n = (prng == 0.f) ? 0.f : (v - pmn) / prng;
                if (n < 0.2f) n = 0.f;                 // THRESH
                rowacc += wx[i - xlo] * n;
            }
            acc += wy * rowacc;
        }
    }
    float val = acc / (wys * wxs);
    g_resized[layer * 57600 + o] = val;
    float mn = val, mx = val, sm = val;
    blockMinMaxSum(mn, mx, sm);
    if (threadIdx.x == 0) {
        atomicMin(&g_rmin[layer], fkey(mn));
        atomicMax(&g_rmax[layer], fkey(mx));
        atomicAdd(&g_rsum[layer], sm);
    }
}

// group = normalize(ponder(resized), 0, 256); out = [sum(240x240)] ++ [groups(240x240x5)]
__global__ void k_final(float* __restrict__ out, int out_size) {
    int o = blockIdx.x * blockDim.x + threadIdx.x;  // < 57600
    float s = 0.f;
    float grp[5];
    #pragma unroll
    for (int l = 0; l < 5; l++) {
        float rmn = funkey(g_rmin[l]), rmx = funkey(g_rmax[l]);
        float rng = rmx - rmn;
        float mean = g_rsum[l] / 57600.0f;
        float w = (rmx - mean); w *= w;
        float v = g_resized[l * 57600 + o];
        float n = (rng == 0.f) ? 0.f : (v - rmn) / rng;
        float pond = n * w;
        // ponder image has exact min 0, max w -> normalize(...,0,256) = pond/w*256
        float g = (w == 0.f || rng == 0.f) ? 0.f : (pond / w * 256.0f);
        grp[l] = g;
        s += g;
    }
    out[o] = s;
    if (out_size >= 345600) {
        float* og = out + 57600;
        #pragma unroll
        for (int l = 0; l < 5; l++) og[o * 5 + l] = grp[l];
    }
}

// ---------------- launch ----------------
extern "C" void kernel_launch(void* const* d_in, const int* in_sizes, int n_in,
                              void* d_out, int out_size) {
    static const int h_C[5]   = {64, 128, 256, 512, 512};
    static const int h_H[5]   = {480, 240, 120, 60, 30};
    static const int h_cb[5]  = {0, 64, 192, 448, 960};
    static const unsigned long long h_gOff[5] =
        {0ULL, 14745600ULL, 22118400ULL, 25804800ULL, 27648000ULL};
    static const int h_pOff[5] = {0, 230400, 288000, 302400, 306000};
    static const int h_S[5]    = {16, 8, 4, 1, 1};

    k_init<<<(TOT_CH * 6 + 255) / 256, 256>>>();

    for (int l = 0; l < 5; l++) {
        dim3 g(h_S[l], h_C[l]);
        k_minmax<<<g, 256>>>((const float*)d_in[l], h_H[l], h_cb[l], h_S[l]);
    }
    for (int l = 0; l < 5; l++) {
        dim3 g(h_S[l], h_C[l]);
        k_hist<<<g, 256>>>((const float*)d_in[l], h_H[l], h_cb[l], h_gOff[l], h_S[l]);
    }
    k_tables<<<(TOT_CH + 127) / 128, 128>>>();
    for (int l = 0; l < 5; l++) {
        int HW = h_H[l] * h_H[l];
        k_proc<<<(HW + 255) / 256, 256>>>(h_C[l], h_H[l], h_cb[l], h_gOff[l], h_pOff[l], l);
    }
    for (int l = 0; l < 5; l++)
        k_resize<<<225, 256>>>(h_H[l], h_pOff[l], l);
    k_final<<<225, 256>>>((float*)d_out, out_size);
}

// round 3
// speedup vs baseline: 2.4506x; 2.4506x over previous
#include <cuda_runtime.h>
#include <math.h>

// ---------------- static scratch ----------------
#define TOT_CH 1472
#define EXC_CAP (1 << 21)

__device__ unsigned int g_chmin[TOT_CH], g_chmax[TOT_CH];   // ordered-key float
__device__ int          g_cnt[TOT_CH][6];    // cnt_k = #(val >= T_k), k=1..5
__device__ int          g_cg[TOT_CH][6];     // exception gidx counts (g<5)
__device__ float        g_ptab[TOT_CH][6];
__device__ float        g_pborder[TOT_CH];
__device__ float        g_S5[5], g_Bc[5];    // interior / border proc constants
__device__ int          g_excCnt[5];
__device__ unsigned int g_exc[5 * EXC_CAP];  // packed: p[0:18) | c[18:27) | g[27:30)
__device__ float        g_proc[306900];
__device__ unsigned int g_procmin[5], g_procmax[5];
__device__ float        g_resized[5 * 57600];
__device__ unsigned int g_rmin[5], g_rmax[5];
__device__ float        g_rsum[5];

__device__ __forceinline__ unsigned fkey(float f) {
    unsigned u = __float_as_uint(f);
    return (u & 0x80000000u) ? ~u : (u | 0x80000000u);
}
__device__ __forceinline__ float funkey(unsigned u) {
    return (u & 0x80000000u) ? __uint_as_float(u & 0x7fffffffu) : __uint_as_float(~u);
}
__device__ __forceinline__ float wrMin(float v) {
    #pragma unroll
    for (int o = 16; o; o >>= 1) v = fminf(v, __shfl_xor_sync(0xffffffffu, v, o));
    return v;
}
__device__ __forceinline__ float wrMax(float v) {
    #pragma unroll
    for (int o = 16; o; o >>= 1) v = fmaxf(v, __shfl_xor_sync(0xffffffffu, v, o));
    return v;
}
__device__ __forceinline__ float wrSum(float v) {
    #pragma unroll
    for (int o = 16; o; o >>= 1) v += __shfl_xor_sync(0xffffffffu, v, o);
    return v;
}
__device__ void blockMinMax(float& mn, float& mx) {
    __shared__ float smn[8], smx[8];
    int lane = threadIdx.x & 31, w = threadIdx.x >> 5;
    mn = wrMin(mn); mx = wrMax(mx);
    if (lane == 0) { smn[w] = mn; smx[w] = mx; }
    __syncthreads();
    if (threadIdx.x < 8) { mn = smn[threadIdx.x]; mx = smx[threadIdx.x]; }
    else { mn = INFINITY; mx = -INFINITY; }
    if (w == 0) { mn = wrMin(mn); mx = wrMax(mx); }
}
__device__ void blockMinMaxSum(float& mn, float& mx, float& sm) {
    __shared__ float smn[8], smx[8], ssm[8];
    int lane = threadIdx.x & 31, w = threadIdx.x >> 5;
    mn = wrMin(mn); mx = wrMax(mx); sm = wrSum(sm);
    if (lane == 0) { smn[w] = mn; smx[w] = mx; ssm[w] = sm; }
    __syncthreads();
    if (threadIdx.x < 8) { mn = smn[threadIdx.x]; mx = smx[threadIdx.x]; sm = ssm[threadIdx.x]; }
    else { mn = INFINITY; mx = -INFINITY; sm = 0.f; }
    if (w == 0) { mn = wrMin(mn); mx = wrMax(mx); sm = wrSum(sm); }
}

// ---------------- kernels ----------------

__global__ void k_init() {
    int i = blockIdx.x * blockDim.x + threadIdx.x;
    if (i < TOT_CH) { g_chmin[i] = 0xFFFFFFFFu; g_chmax[i] = 0u; }
    if (i < TOT_CH * 6) { ((int*)g_cnt)[i] = 0; ((int*)g_cg)[i] = 0; }
    if (i < 5) {
        g_excCnt[i] = 0; g_S5[i] = 0.f; g_Bc[i] = 0.f;
        g_procmin[i] = 0xFFFFFFFFu; g_procmax[i] = 0u;
        g_rmin[i] = 0xFFFFFFFFu; g_rmax[i] = 0u; g_rsum[i] = 0.f;
    }
}

// interior rows, vectorized, div-free min/max (border zeros folded via init 0)
template <int W, int H, int VEC>
__global__ void k_minmax(const float* __restrict__ in, int chanBase) {
    constexpr int Wc = W / VEC;
    constexpr int Nc = (H - 2) * Wc;
    int c = blockIdx.y;
    const float* ch = in + (size_t)c * H * W;
    float vmn = 0.f, vmx = 0.f;  // include border zeros
    int stride = gridDim.x * blockDim.x;
    for (int i = blockIdx.x * blockDim.x + threadIdx.x; i < Nc; i += stride) {
        int q = i / Wc;
        int xc = i - q * Wc;
        const float* pv = ch + (q + 1) * W + xc * VEC;
        float v[VEC];
        if (VEC == 4) {
            float4 t = *(const float4*)pv;
            v[0] = t.x; v[1] = t.y; v[2] = t.z; v[3] = t.w;
        } else {
            float2 t = *(const float2*)pv;
            v[0] = t.x; v[1] = t.y;
        }
        if (xc == 0) v[0] = 0.f;
        if (xc == Wc - 1) v[VEC - 1] = 0.f;
        #pragma unroll
        for (int s = 0; s < VEC; s++) { vmn = fminf(vmn, v[s]); vmx = fmaxf(vmx, v[s]); }
    }
    blockMinMax(vmn, vmx);
    if (threadIdx.x == 0) {
        atomicMin(&g_chmin[chanBase + c], fkey(vmn));
        atomicMax(&g_chmax[chanBase + c], fkey(vmx));
    }
}

// threshold-ballot histogram + rare-gidx exception capture
template <int W, int H, int VEC>
__global__ void k_hist(const float* __restrict__ in, int chanBase, int layer) {
    constexpr int Wc = W / VEC;
    constexpr int Nc = (H - 2) * Wc;
    int c = blockIdx.y;
    int gch = chanBase + c;
    const float* ch = in + (size_t)c * H * W;
    float mn = funkey(g_chmin[gch]);
    float mx = funkey(g_chmax[gch]);
    float rng = mx - mn;
    if (rng == 0.f) return;  // all-zero channel: contributes nothing (tables handles)
    float T1 = mn + rng * (1.f / 6.f), T2 = mn + rng * (2.f / 6.f),
          T3 = mn + rng * (3.f / 6.f), T4 = mn + rng * (4.f / 6.f),
          T5 = mn + rng * (5.f / 6.f);
    float Texc = mn + rng * (1.5f / 256.f);  // widened g<5 candidate band

    int c1 = 0, c2 = 0, c3 = 0, c4 = 0, c5 = 0;
    int base = blockIdx.x * blockDim.x + threadIdx.x;
    int stride = gridDim.x * blockDim.x;
    int iters = (Nc + stride - 1) / stride;

    for (int t = 0; t < iters; t++) {
        int i = base + t * stride;
        bool inR = i < Nc;
        int ii = inR ? i : 0;
        int q = ii / Wc;
        int xc = ii - q * Wc;
        float v[VEC];
        if (inR) {
            const float* pv = ch + (q + 1) * W + xc * VEC;
            if (VEC == 4) {
                float4 tv = *(const float4*)pv;
                v[0] = tv.x; v[1] = tv.y; v[2] = tv.z; v[3] = tv.w;
            } else {
                float2 tv = *(const float2*)pv;
                v[0] = tv.x; v[1] = tv.y;
            }
            if (xc == 0) v[0] = -1.f;           // x-border: excluded (analytic)
            if (xc == Wc - 1) v[VEC - 1] = -1.f;
        } else {
            #pragma unroll
            for (int s = 0; s < VEC; s++) v[s] = -1.f;
        }
        bool e[VEC]; bool anyE = false;
        #pragma unroll
        for (int s = 0; s < VEC; s++) {
            float val = v[s];
            c1 += __popc(__ballot_sync(0xffffffffu, val >= T1));
            c2 += __popc(__ballot_sync(0xffffffffu, val >= T2));
            c3 += __popc(__ballot_sync(0xffffffffu, val >= T3));
            c4 += __popc(__ballot_sync(0xffffffffu, val >= T4));
            c5 += __popc(__ballot_sync(0xffffffffu, val >= T5));
            e[s] = (val < Texc) && (val >= 0.f);
            anyE = anyE || e[s];
        }
        if (__any_sync(0xffffffffu, anyE)) {
            #pragma unroll
            for (int s = 0; s < VEC; s++) {
                if (e[s]) {
                    // exact jnp arithmetic for the rare path
                    float vn = __fmul_rn(__fdiv_rn(__fsub_rn(v[s], mn), rng), 256.0f);
                    int g = (int)truncf(__fsub_rn(__fmul_rn(vn, 6.0f), 1.0f));
                    g = max(0, min(5, g));
                    if (g < 5) {
                        atomicAdd(&g_cg[gch][g], 1);
                        int idx = atomicAdd(&g_excCnt[layer], 1);
                        if (idx < EXC_CAP) {
                            int p = (q + 1) * W + xc * VEC + s;
                            g_exc[layer * EXC_CAP + idx] =
                                (unsigned)p | ((unsigned)c << 18) | ((unsigned)g << 27);
                        }
                    }
                }
            }
        }
    }
    if ((threadIdx.x & 31) == 0) {  // ballot results identical across the warp
        atomicAdd(&g_cnt[gch][1], c1); atomicAdd(&g_cnt[gch][2], c2);
        atomicAdd(&g_cnt[gch][3], c3); atomicAdd(&g_cnt[gch][4], c4);
        atomicAdd(&g_cnt[gch][5], c5);
    }
}

// per-channel table math (border pixels: bin0 / gidx0, handled analytically)
__global__ void k_tables() {
    int ch = blockIdx.x * blockDim.x + threadIdx.x;
    if (ch >= TOT_CH) return;
    const int cbnd[6] = {0, 64, 192, 448, 960, 1472};
    const int Hs[5] = {480, 240, 120, 60, 30};
    int layer = 0;
    #pragma unroll
    for (int l = 1; l < 5; l++) if (ch >= cbnd[l]) layer = l;
    int cIn = ch - cbnd[layer];
    int H = Hs[layer], HW = H * H, nb = 4 * H - 4, Nin = (H - 2) * (H - 2);

    float mn = funkey(g_chmin[ch]), mx = funkey(g_chmax[ch]);
    float ptab[6] = {0, 0, 0, 0, 0, 0};
    float pb = 0.f;

    if (mx - mn != 0.f) {
        int n1 = g_cnt[ch][1], n2 = g_cnt[ch][2], n3 = g_cnt[ch][3],
            n4 = g_cnt[ch][4], n5 = g_cnt[ch][5];
        int cb[6];
        cb[0] = Nin - n1 + nb; cb[1] = n1 - n2; cb[2] = n2 - n3;
        cb[3] = n3 - n4; cb[4] = n4 - n5; cb[5] = n5;
        int cg[6]; int sumE = 0;
        #pragma unroll
        for (int g = 0; g < 5; g++) { cg[g] = g_cg[ch][g]; sumE += cg[g]; }
        cg[5] = Nin - sumE;
        cg[0] += nb;  // border pixels: gidx 0

        float hv[6];
        #pragma unroll
        for (int b = 0; b < 6; b++)
            hv[b] = -logf((float)cb[b] / (float)HW + 1e-4f);

        float dmn = INFINITY, dmx = -INFINITY;
        #pragma unroll
        for (int g = 0; g < 6; g++) if (cg[g] > 0) { dmn = fminf(dmn, hv[g]); dmx = fmaxf(dmx, hv[g]); }
        float drng = dmx - dmn;
        float dst[6];
        #pragma unroll
        for (int g = 0; g < 6; g++) dst[g] = (drng == 0.f) ? 0.f : (hv[g] - dmn) / drng;
        float meanD = 0.f;
        #pragma unroll
        for (int g = 0; g < 6; g++) meanD += (float)cg[g] * dst[g];
        meanD /= (float)HW;
        float maxD = -INFINITY;
        #pragma unroll
        for (int g = 0; g < 6; g++) if (cg[g] > 0) maxD = fmaxf(maxD, dst[g]);
        float wr = (maxD - meanD); wr *= wr;
        float rt[6];
        #pragma unroll
        for (int g = 0; g < 6; g++) rt[g] = dst[g] * wr;

        // maps stats: c==0 keeps border (value rt[0]); c>=1 border zeroed
        float mmn, mmx, msum = 0.f;
        if (cIn == 0) {
            mmn = INFINITY; mmx = -INFINITY;
            #pragma unroll
            for (int g = 0; g < 6; g++) if (cg[g] > 0) {
                mmn = fminf(mmn, rt[g]); mmx = fmaxf(mmx, rt[g]);
                msum += (float)cg[g] * rt[g];
            }
        } else {
            mmn = 0.f; mmx = 0.f;
            #pragma unroll
            for (int g = 0; g < 6; g++) {
                int ci = cg[g] - ((g == 0) ? nb : 0);
                if (ci > 0) { mmn = fminf(mmn, rt[g]); mmx = fmaxf(mmx, rt[g]); msum += (float)ci * rt[g]; }
            }
        }
        float mrng = mmx - mmn;
        float wp = mmx - msum / (float)HW; wp *= wp;
        #pragma unroll
        for (int g = 0; g < 6; g++)
            ptab[g] = (mrng == 0.f) ? 0.f : ((rt[g] - mmn) / mrng) * wp;
        pb = (cIn == 0) ? 0.f : ((mrng == 0.f) ? 0.f : ((0.f - mmn) / mrng) * wp);
    }
    #pragma unroll
    for (int g = 0; g < 6; g++) g_ptab[ch][g] = ptab[g];
    g_pborder[ch] = pb;
    atomicAdd(&g_S5[layer], ptab[5]);
    atomicAdd(&g_Bc[layer], (cIn == 0) ? ptab[0] : pb);
}

__global__ void k_procfill() {
    int i = blockIdx.x * blockDim.x + threadIdx.x;
    if (i >= 306900) return;
    const int pOff[6] = {0, 230400, 288000, 302400, 306000, 306900};
    const int Hs[5] = {480, 240, 120, 60, 30};
    int layer = 0;
    #pragma unroll
    for (int l = 1; l < 5; l++) if (i >= pOff[l]) layer = l;
    int p = i - pOff[layer];
    int W = Hs[layer];
    int y = p / W, x = p - y * W;
    bool border = (y == 0 || x == 0 || y == W - 1 || x == W - 1);
    g_proc[i] = border ? g_Bc[layer] : g_S5[layer];
}

__global__ void k_scatter() {
    const int pOff[5] = {0, 230400, 288000, 302400, 306000};
    const int cbnd[5] = {0, 64, 192, 448, 960};
    int tid = blockIdx.x * blockDim.x + threadIdx.x;
    int stride = gridDim.x * blockDim.x;
    for (int l = 0; l < 5; l++) {
        int n = min(g_excCnt[l], EXC_CAP);
        for (int j = tid; j < n; j += stride) {
            unsigned e = g_exc[l * EXC_CAP + j];
            int p = e & 0x3FFFF;
            int c = (e >> 18) & 0x1FF;
            int g = (e >> 27) & 7;
            float d = g_ptab[cbnd[l] + c][g] - g_ptab[cbnd[l] + c][5];
            atomicAdd(&g_proc[pOff[l] + p], d);
        }
    }
}

__global__ void k_procstats() {
    const int pOff[5] = {0, 230400, 288000, 302400, 306000};
    const int HWs[5] = {230400, 57600, 14400, 3600, 900};
    int layer = blockIdx.y;
    int i = blockIdx.x * blockDim.x + threadIdx.x;
    float mn = INFINITY, mx = -INFINITY;
    if (i < HWs[layer]) { float v = g_proc[pOff[layer] + i]; mn = v; mx = v; }
    blockMinMax(mn, mx);
    if (threadIdx.x == 0) {
        atomicMin(&g_procmin[layer], fkey(mn));
        atomicMax(&g_procmax[layer], fkey(mx));
    }
}

// jax.image.resize (linear, antialias) of thresholded normalized proc -> 240x240
__global__ void k_resize() {
    const int pOff[5] = {0, 230400, 288000, 302400, 306000};
    const int Hs[5] = {480, 240, 120, 60, 30};
    int layer = blockIdx.y;
    int H = Hs[layer], W = H;
    int o = blockIdx.x * blockDim.x + threadIdx.x;  // 0..57599
    float pmn = funkey(g_procmin[layer]);
    float pmx = funkey(g_procmax[layer]);
    float prng = pmx - pmn;
    int oy = o / 240, ox = o - oy * 240;
    float inv = (float)H / 240.0f;
    float ks = fmaxf(inv, 1.0f);
    float fy = ((float)oy + 0.5f) * inv - 0.5f;
    float fx = ((float)ox + 0.5f) * inv - 0.5f;
    int ylo = max(0, (int)ceilf(fy - ks)), yhi = min(H - 1, (int)floorf(fy + ks));
    int xlo = max(0, (int)ceilf(fx - ks)), xhi = min(W - 1, (int)floorf(fx + ks));
    float wx[8]; float wxs = 0.f;
    for (int j = xlo; j <= xhi; j++) {
        float w = fmaxf(0.f, 1.0f - fabsf(fx - (float)j) / ks);
        wx[j - xlo] = w; wxs += w;
    }
    const float* pr = g_proc + pOff[layer];
    float acc = 0.f, wys = 0.f;
    for (int j = ylo; j <= yhi; j++) {
        float wy = fmaxf(0.f, 1.0f - fabsf(fy - (float)j) / ks);
        wys += wy;
        if (wy != 0.f) {
            float rowacc = 0.f;
            for (int i = xlo; i <= xhi; i++) {
                float v = pr[j * W + i];
                float n = (prng == 0.f) ? 0.f : (v - pmn) / prng;
                if (n < 0.2f) n = 0.f;
                rowacc += wx[i - xlo] * n;
            }
            acc += wy * rowacc;
        }
    }
    float val = acc / (wys * wxs);
    g_resized[layer * 57600 + o] = val;
    float mn = val, mx = val, sm = val;
    blockMinMaxSum(mn, mx, sm);
    if (threadIdx.x == 0) {
        atomicMin(&g_rmin[layer], fkey(mn));
        atomicMax(&g_rmax[layer], fkey(mx));
        atomicAdd(&g_rsum[layer], sm);
    }
}

__global__ void k_final(float* __restrict__ out, int out_size) {
    int o = blockIdx.x * blockDim.x + threadIdx.x;
    float s = 0.f;
    float grp[5];
    #pragma unroll
    for (int l = 0; l < 5; l++) {
        float rmn = funkey(g_rmin[l]), rmx = funkey(g_rmax[l]);
        float rng = rmx - rmn;
        float mean = g_rsum[l] / 57600.0f;
        float w = (rmx - mean); w *= w;
        float v = g_resized[l * 57600 + o];
        float n = (rng == 0.f) ? 0.f : (v - rmn) / rng;
        float g = (w == 0.f || rng == 0.f) ? 0.f : (n * w / w * 256.0f);
        grp[l] = g;
        s += g;
    }
    out[o] = s;
    if (out_size >= 345600) {
        float* og = out + 57600;
        #pragma unroll
        for (int l = 0; l < 5; l++) og[o * 5 + l] = grp[l];
    }
}

// ---------------- launch ----------------
extern "C" void kernel_launch(void* const* d_in, const int* in_sizes, int n_in,
                              void* d_out, int out_size) {
    k_init<<<(TOT_CH * 6 + 255) / 256, 256>>>();

    const float* l0 = (const float*)d_in[0];
    const float* l1 = (const float*)d_in[1];
    const float* l2 = (const float*)d_in[2];
    const float* l3 = (const float*)d_in[3];
    const float* l4 = (const float*)d_in[4];

    // per-layer interleave so the hist pass hits L2-resident data
    k_minmax<480, 480, 4><<<dim3(16, 64), 256>>>(l0, 0);
    k_hist<480, 480, 4><<<dim3(16, 64), 256>>>(l0, 0, 0);
    k_minmax<240, 240, 4><<<dim3(8, 128), 256>>>(l1, 64);
    k_hist<240, 240, 4><<<dim3(8, 128), 256>>>(l1, 64, 1);
    k_minmax<120, 120, 4><<<dim3(4, 256), 256>>>(l2, 192);
    k_hist<120, 120, 4><<<dim3(4, 256), 256>>>(l2, 192, 2);
    k_minmax<60, 60, 4><<<dim3(1, 512), 256>>>(l3, 448);
    k_hist<60, 60, 4><<<dim3(1, 512), 256>>>(l3, 448, 3);
    k_minmax<30, 30, 2><<<dim3(1, 512), 256>>>(l4, 960);
    k_hist<30, 30, 2><<<dim3(1, 512), 256>>>(l4, 960, 4);

    k_tables<<<(TOT_CH + 127) / 128, 128>>>();
    k_procfill<<<(306900 + 255) / 256, 256>>>();
    k_scatter<<<256, 256>>>();
    k_procstats<<<dim3(900, 5), 256>>>();
    k_resize<<<dim3(225, 5), 256>>>();
    k_final<<<225, 256>>>((float*)d_out, out_size);
}

// round 5
// speedup vs baseline: 2.8999x; 1.1834x over previous
#include <cuda_runtime.h>
#include <math.h>

// ---------------- static scratch ----------------
#define TOT_CH 1472
#define EXC_CAP (1 << 21)

__device__ unsigned int g_chmin[TOT_CH], g_chmax[TOT_CH];   // ordered-key float
__device__ int          g_cnt[TOT_CH][6];    // cnt_k = #(val >= T_k), k=1..5
__device__ int          g_cg[TOT_CH][6];     // exception gidx counts (g<5)
__device__ float        g_ptab[TOT_CH][6];
__device__ float        g_pborder[TOT_CH];
__device__ float        g_S5[5], g_Bc[5];    // interior / border proc constants
__device__ int          g_excCnt[5];
__device__ unsigned int g_exc[5 * EXC_CAP];  // packed: p[0:18) | c[18:27) | g[27:30)
__device__ float        g_proc[306900];
__device__ unsigned int g_procmin[5], g_procmax[5];
__device__ float        g_resized[5 * 57600];
__device__ unsigned int g_rmin[5], g_rmax[5];
__device__ float        g_rsum[5];

__device__ __forceinline__ unsigned fkey(float f) {
    unsigned u = __float_as_uint(f);
    return (u & 0x80000000u) ? ~u : (u | 0x80000000u);
}
__device__ __forceinline__ float funkey(unsigned u) {
    return (u & 0x80000000u) ? __uint_as_float(u & 0x7fffffffu) : __uint_as_float(~u);
}
__device__ __forceinline__ float wrMin(float v) {
    #pragma unroll
    for (int o = 16; o; o >>= 1) v = fminf(v, __shfl_xor_sync(0xffffffffu, v, o));
    return v;
}
__device__ __forceinline__ float wrMax(float v) {
    #pragma unroll
    for (int o = 16; o; o >>= 1) v = fmaxf(v, __shfl_xor_sync(0xffffffffu, v, o));
    return v;
}
__device__ __forceinline__ float wrSum(float v) {
    #pragma unroll
    for (int o = 16; o; o >>= 1) v += __shfl_xor_sync(0xffffffffu, v, o);
    return v;
}
__device__ __forceinline__ int wrSumI(int v) {
    #pragma unroll
    for (int o = 16; o; o >>= 1) v += __shfl_xor_sync(0xffffffffu, v, o);
    return v;
}
__device__ void blockMinMax(float& mn, float& mx) {
    __shared__ float smn[8], smx[8];
    int lane = threadIdx.x & 31, w = threadIdx.x >> 5;
    mn = wrMin(mn); mx = wrMax(mx);
    if (lane == 0) { smn[w] = mn; smx[w] = mx; }
    __syncthreads();
    if (threadIdx.x < 8) { mn = smn[threadIdx.x]; mx = smx[threadIdx.x]; }
    else { mn = INFINITY; mx = -INFINITY; }
    if (w == 0) { mn = wrMin(mn); mx = wrMax(mx); }
}
__device__ void blockMinMaxSum(float& mn, float& mx, float& sm) {
    __shared__ float smn[8], smx[8], ssm[8];
    int lane = threadIdx.x & 31, w = threadIdx.x >> 5;
    mn = wrMin(mn); mx = wrMax(mx); sm = wrSum(sm);
    if (lane == 0) { smn[w] = mn; smx[w] = mx; ssm[w] = sm; }
    __syncthreads();
    if (threadIdx.x < 8) { mn = smn[threadIdx.x]; mx = smx[threadIdx.x]; sm = ssm[threadIdx.x]; }
    else { mn = INFINITY; mx = -INFINITY; sm = 0.f; }
    if (w == 0) { mn = wrMin(mn); mx = wrMax(mx); sm = wrSum(sm); }
}

// ---------------- kernels ----------------

__global__ void k_init() {
    int i = blockIdx.x * blockDim.x + threadIdx.x;
    if (i < TOT_CH) { g_chmin[i] = 0xFFFFFFFFu; g_chmax[i] = 0u; }
    if (i < TOT_CH * 6) { ((int*)g_cnt)[i] = 0; ((int*)g_cg)[i] = 0; }
    if (i < 5) {
        g_excCnt[i] = 0; g_S5[i] = 0.f; g_Bc[i] = 0.f;
        g_procmin[i] = 0xFFFFFFFFu; g_procmax[i] = 0u;
        g_rmin[i] = 0xFFFFFFFFu; g_rmax[i] = 0u; g_rsum[i] = 0.f;
    }
}

// ---- fused min/max pass ----
template <int W, int H, int VEC>
__device__ __forceinline__ void minmax_body(const float* __restrict__ in,
                                            int chanBase, int widx, int splits) {
    constexpr int Wc = W / VEC;
    constexpr int Nc = (H - 2) * Wc;
    int c = widx / splits;
    int sp = widx - c * splits;
    const float* ch = in + (size_t)c * H * W;
    int chunk = (Nc + splits - 1) / splits;
    int lo = sp * chunk, hi = min(Nc, lo + chunk);
    float mn0 = 0.f, mx0 = 0.f, mn1 = 0.f, mx1 = 0.f;  // include border zeros
    for (int i = lo + threadIdx.x; i < hi; i += 256) {
        int q = i / Wc;
        int xc = i - q * Wc;
        const float* pv = ch + (q + 1) * W + xc * VEC;
        float v[VEC];
        if (VEC == 4) {
            float4 t = *(const float4*)pv;
            v[0] = t.x; v[1] = t.y; v[2] = t.z; v[3] = t.w;
        } else {
            float2 t = *(const float2*)pv;
            v[0] = t.x; v[1] = t.y;
        }
        if (xc == 0) v[0] = 0.f;
        if (xc == Wc - 1) v[VEC - 1] = 0.f;
        #pragma unroll
        for (int s = 0; s < VEC; s += 2) { mn0 = fminf(mn0, v[s]); mx0 = fmaxf(mx0, v[s]); }
        #pragma unroll
        for (int s = 1; s < VEC; s += 2) { mn1 = fminf(mn1, v[s]); mx1 = fmaxf(mx1, v[s]); }
    }
    float vmn = fminf(mn0, mn1), vmx = fmaxf(mx0, mx1);
    blockMinMax(vmn, vmx);
    if (threadIdx.x == 0) {
        atomicMin(&g_chmin[chanBase + c], fkey(vmn));
        atomicMax(&g_chmax[chanBase + c], fkey(vmx));
    }
}

__global__ void __launch_bounds__(256) k_minmaxAll(
    const float* __restrict__ l0, const float* __restrict__ l1,
    const float* __restrict__ l2, const float* __restrict__ l3,
    const float* __restrict__ l4) {
    int b = blockIdx.x;
    if (b < 1024)      minmax_body<480, 480, 4>(l0, 0,   b,        16);
    else if (b < 1536) minmax_body<240, 240, 4>(l1, 64,  b - 1024, 4);
    else if (b < 1792) minmax_body<120, 120, 4>(l2, 192, b - 1536, 1);
    else if (b < 2304) minmax_body< 60,  60, 4>(l3, 448, b - 1792, 1);
    else               minmax_body< 30,  30, 2>(l4, 960, b - 2304, 1);
}

// ---- fused histogram pass (per-thread predicate counters) ----
template <int W, int H, int VEC>
__device__ __forceinline__ void hist_body(const float* __restrict__ in,
                                          int chanBase, int layer,
                                          int widx, int splits) {
    constexpr int Wc = W / VEC;
    constexpr int Nc = (H - 2) * Wc;
    int c = widx / splits;
    int sp = widx - c * splits;
    int gch = chanBase + c;
    const float* ch = in + (size_t)c * H * W;
    float mn = funkey(g_chmin[gch]);
    float mx = funkey(g_chmax[gch]);
    float rng = mx - mn;
    if (rng == 0.f) return;  // degenerate channel handled in tables
    float T1 = mn + rng * (1.f / 6.f), T2 = mn + rng * (2.f / 6.f),
          T3 = mn + rng * (3.f / 6.f), T4 = mn + rng * (4.f / 6.f),
          T5 = mn + rng * (5.f / 6.f);
    float Texc = mn + rng * (1.5f / 256.f);  // widened g<5 candidate band

    int c1 = 0, c2 = 0, c3 = 0, c4 = 0, c5 = 0;
    int chunk = (Nc + splits - 1) / splits;
    int lo = sp * chunk, hi = min(Nc, lo + chunk);

    for (int i = lo + threadIdx.x; i < hi; i += 256) {
        int q = i / Wc;
        int xc = i - q * Wc;
        const float* pv = ch + (q + 1) * W + xc * VEC;
        float v[VEC];
        if (VEC == 4) {
            float4 tv = *(const float4*)pv;
            v[0] = tv.x; v[1] = tv.y; v[2] = tv.z; v[3] = tv.w;
        } else {
            float2 tv = *(const float2*)pv;
            v[0] = tv.x; v[1] = tv.y;
        }
        if (xc == 0) v[0] = -1.f;           // x-border: excluded (analytic)
        if (xc == Wc - 1) v[VEC - 1] = -1.f;
        #pragma unroll
        for (int s = 0; s < VEC; s++) {
            float val = v[s];
            c1 += (val >= T1); c2 += (val >= T2); c3 += (val >= T3);
            c4 += (val >= T4); c5 += (val >= T5);
            if (val >= 0.f && val < Texc) {
                // exact jnp arithmetic for the rare path
                float vn = __fmul_rn(__fdiv_rn(__fsub_rn(val, mn), rng), 256.0f);
                int g = (int)truncf(__fsub_rn(__fmul_rn(vn, 6.0f), 1.0f));
                g = max(0, min(5, g));
                if (g < 5) {
                    atomicAdd(&g_cg[gch][g], 1);
                    int idx = atomicAdd(&g_excCnt[layer], 1);
                    if (idx < EXC_CAP) {
                        int p = (q + 1) * W + xc * VEC + s;
                        g_exc[layer * EXC_CAP + idx] =
                            (unsigned)p | ((unsigned)c << 18) | ((unsigned)g << 27);
                    }
                }
            }
        }
    }
    c1 = wrSumI(c1); c2 = wrSumI(c2); c3 = wrSumI(c3);
    c4 = wrSumI(c4); c5 = wrSumI(c5);
    if ((threadIdx.x & 31) == 0) {
        atomicAdd(&g_cnt[gch][1], c1); atomicAdd(&g_cnt[gch][2], c2);
        atomicAdd(&g_cnt[gch][3], c3); atomicAdd(&g_cnt[gch][4], c4);
        atomicAdd(&g_cnt[gch][5], c5);
    }
}

__global__ void __launch_bounds__(256) k_histAll(
    const float* __restrict__ l0, const float* __restrict__ l1,
    const float* __restrict__ l2, const float* __restrict__ l3,
    const float* __restrict__ l4) {
    int b = blockIdx.x;
    if (b < 1024)      hist_body<480, 480, 4>(l0, 0,   0, b,        16);
    else if (b < 1536) hist_body<240, 240, 4>(l1, 64,  1, b - 1024, 4);
    else if (b < 1792) hist_body<120, 120, 4>(l2, 192, 2, b - 1536, 1);
    else if (b < 2304) hist_body< 60,  60, 4>(l3, 448, 3, b - 1792, 1);
    else               hist_body< 30,  30, 2>(l4, 960, 4, b - 2304, 1);
}

// per-channel table math (border pixels: bin0 / gidx0, handled analytically)
__global__ void k_tables() {
    int ch = blockIdx.x * blockDim.x + threadIdx.x;
    if (ch >= TOT_CH) return;
    const int cbnd[6] = {0, 64, 192, 448, 960, 1472};
    const int Hs[5] = {480, 240, 120, 60, 30};
    int layer = 0;
    #pragma unroll
    for (int l = 1; l < 5; l++) if (ch >= cbnd[l]) layer = l;
    int cIn = ch - cbnd[layer];
    int H = Hs[layer], HW = H * H, nb = 4 * H - 4, Nin = (H - 2) * (H - 2);

    float mn = funkey(g_chmin[ch]), mx = funkey(g_chmax[ch]);
    float ptab[6] = {0, 0, 0, 0, 0, 0};
    float pb = 0.f;

    if (mx - mn != 0.f) {
        int n1 = g_cnt[ch][1], n2 = g_cnt[ch][2], n3 = g_cnt[ch][3],
            n4 = g_cnt[ch][4], n5 = g_cnt[ch][5];
        int cb[6];
        cb[0] = Nin - n1 + nb; cb[1] = n1 - n2; cb[2] = n2 - n3;
        cb[3] = n3 - n4; cb[4] = n4 - n5; cb[5] = n5;
        int cg[6]; int sumE = 0;
        #pragma unroll
        for (int g = 0; g < 5; g++) { cg[g] = g_cg[ch][g]; sumE += cg[g]; }
        cg[5] = Nin - sumE;
        cg[0] += nb;  // border pixels: gidx 0

        float hv[6];
        #pragma unroll
        for (int b = 0; b < 6; b++)
            hv[b] = -logf((float)cb[b] / (float)HW + 1e-4f);

        float dmn = INFINITY, dmx = -INFINITY;
        #pragma unroll
        for (int g = 0; g < 6; g++) if (cg[g] > 0) { dmn = fminf(dmn, hv[g]); dmx = fmaxf(dmx, hv[g]); }
        float drng = dmx - dmn;
        float dst[6];
        #pragma unroll
        for (int g = 0; g < 6; g++) dst[g] = (drng == 0.f) ? 0.f : (hv[g] - dmn) / drng;
        float meanD = 0.f;
        #pragma unroll
        for (int g = 0; g < 6; g++) meanD += (float)cg[g] * dst[g];
        meanD /= (float)HW;
        float maxD = -INFINITY;
        #pragma unroll
        for (int g = 0; g < 6; g++) if (cg[g] > 0) maxD = fmaxf(maxD, dst[g]);
        float wr = (maxD - meanD); wr *= wr;
        float rt[6];
        #pragma unroll
        for (int g = 0; g < 6; g++) rt[g] = dst[g] * wr;

        // maps stats: c==0 keeps border (value rt[0]); c>=1 border zeroed
        float mmn, mmx, msum = 0.f;
        if (cIn == 0) {
            mmn = INFINITY; mmx = -INFINITY;
            #pragma unroll
            for (int g = 0; g < 6; g++) if (cg[g] > 0) {
                mmn = fminf(mmn, rt[g]); mmx = fmaxf(mmx, rt[g]);
                msum += (float)cg[g] * rt[g];
            }
        } else {
            mmn = 0.f; mmx = 0.f;
            #pragma unroll
            for (int g = 0; g < 6; g++) {
                int ci = cg[g] - ((g == 0) ? nb : 0);
                if (ci > 0) { mmn = fminf(mmn, rt[g]); mmx = fmaxf(mmx, rt[g]); msum += (float)ci * rt[g]; }
            }
        }
        float mrng = mmx - mmn;
        float wp = mmx - msum / (float)HW; wp *= wp;
        #pragma unroll
        for (int g = 0; g < 6; g++)
            ptab[g] = (mrng == 0.f) ? 0.f : ((rt[g] - mmn) / mrng) * wp;
        pb = (cIn == 0) ? 0.f : ((mrng == 0.f) ? 0.f : ((0.f - mmn) / mrng) * wp);
    }
    #pragma unroll
    for (int g = 0; g < 6; g++) g_ptab[ch][g] = ptab[g];
    g_pborder[ch] = pb;
    atomicAdd(&g_S5[layer], ptab[5]);
    atomicAdd(&g_Bc[layer], (cIn == 0) ? ptab[0] : pb);
}

__global__ void k_procfill() {
    int i = blockIdx.x * blockDim.x + threadIdx.x;
    if (i >= 306900) return;
    const int pOff[6] = {0, 230400, 288000, 302400, 306000, 306900};
    const int Hs[5] = {480, 240, 120, 60, 30};
    int layer = 0;
    #pragma unroll
    for (int l = 1; l < 5; l++) if (i >= pOff[l]) layer = l;
    int p = i - pOff[layer];
    int W = Hs[layer];
    int y = p / W, x = p - y * W;
    bool border = (y == 0 || x == 0 || y == W - 1 || x == W - 1);
    g_proc[i] = border ? g_Bc[layer] : g_S5[layer];
}

__global__ void k_scatter() {
    const int pOff[5] = {0, 230400, 288000, 302400, 306000};
    const int cbnd[5] = {0, 64, 192, 448, 960};
    int tid = blockIdx.x * blockDim.x + threadIdx.x;
    int stride = gridDim.x * blockDim.x;
    for (int l = 0; l < 5; l++) {
        int n = min(g_excCnt[l], EXC_CAP);
        for (int j = tid; j < n; j += stride) {
            unsigned e = g_exc[l * EXC_CAP + j];
            int p = e & 0x3FFFF;
            int c = (e >> 18) & 0x1FF;
            int g = (e >> 27) & 7;
            float d = g_ptab[cbnd[l] + c][g] - g_ptab[cbnd[l] + c][5];
            atomicAdd(&g_proc[pOff[l] + p], d);
        }
    }
}

__global__ void k_procstats() {
    // fused block ranges: l0:900, l1:225, l2:57, l3:15, l4:4
    const int pOff[5] = {0, 230400, 288000, 302400, 306000};
    const int HWs[5] = {230400, 57600, 14400, 3600, 900};
    const int bLo[6] = {0, 900, 1125, 1182, 1197, 1201};
    int b = blockIdx.x;
    int layer = 0;
    #pragma unroll
    for (int l = 1; l < 5; l++) if (b >= bLo[l]) layer = l;
    int i = (b - bLo[layer]) * blockDim.x + threadIdx.x;
    float mn = INFINITY, mx = -INFINITY;
    if (i < HWs[layer]) { float v = g_proc[pOff[layer] + i]; mn = v; mx = v; }
    blockMinMax(mn, mx);
    if (threadIdx.x == 0) {
        atomicMin(&g_procmin[layer], fkey(mn));
        atomicMax(&g_procmax[layer], fkey(mx));
    }
}

// jax.image.resize (linear, antialias) of thresholded normalized proc -> 240x240
__global__ void k_resize() {
    const int pOff[5] = {0, 230400, 288000, 302400, 306000};
    const int Hs[5] = {480, 240, 120, 60, 30};
    int layer = blockIdx.y;
    int H = Hs[layer], W = H;
    int o = blockIdx.x * blockDim.x + threadIdx.x;  // 0..57599
    float pmn = funkey(g_procmin[layer]);
    float pmx = funkey(g_procmax[layer]);
    float prng = pmx - pmn;
    int oy = o / 240, ox = o - oy * 240;
    float inv = (float)H / 240.0f;
    float ks = fmaxf(inv, 1.0f);
    float fy = ((float)oy + 0.5f) * inv - 0.5f;
    float fx = ((float)ox + 0.5f) * inv - 0.5f;
    int ylo = max(0, (int)ceilf(fy - ks)), yhi = min(H - 1, (int)floorf(fy + ks));
    int xlo = max(0, (int)ceilf(fx - ks)), xhi = min(W - 1, (int)floorf(fx + ks));
    float wx[8]; float wxs = 0.f;
    for (int j = xlo; j <= xhi; j++) {
        float w = fmaxf(0.f, 1.0f - fabsf(fx - (float)j) / ks);
        wx[j - xlo] = w; wxs += w;
    }
    const float* pr = g_proc + pOff[layer];
    float acc = 0.f, wys = 0.f;
    for (int j = ylo; j <= yhi; j++) {
        float wy = fmaxf(0.f, 1.0f - fabsf(fy - (float)j) / ks);
        wys += wy;
        if (wy != 0.f) {
            float rowacc = 0.f;
            for (int i = xlo; i <= xhi; i++) {
                float v = pr[j * W + i];
                float n = (prng == 0.f) ? 0.f : (v - pmn) / prng;
                if (n < 0.2f) n = 0.f;
                rowacc += wx[i - xlo] * n;
            }
            acc += wy * rowacc;
        }
    }
    float val = acc / (wys * wxs);
    g_resized[layer * 57600 + o] = val;
    float mn = val, mx = val, sm = val;
    blockMinMaxSum(mn, mx, sm);
    if (threadIdx.x == 0) {
        atomicMin(&g_rmin[layer], fkey(mn));
        atomicMax(&g_rmax[layer], fkey(mx));
        atomicAdd(&g_rsum[layer], sm);
    }
}

__global__ void k_final(float* __restrict__ out, int out_size) {
    int o = blockIdx.x * blockDim.x + threadIdx.x;
    float s = 0.f;
    float grp[5];
    #pragma unroll
    for (int l = 0; l < 5; l++) {
        float rmn = funkey(g_rmin[l]), rmx = funkey(g_rmax[l]);
        float rng = rmx - rmn;
        float mean = g_rsum[l] / 57600.0f;
        float w = (rmx - mean); w *= w;
        float v = g_resized[l * 57600 + o];
        float n = (rng == 0.f) ? 0.f : (v - rmn) / rng;
        float g = (w == 0.f || rng == 0.f) ? 0.f : (n * w / w * 256.0f);
        grp[l] = g;
        s += g;
    }
    out[o] = s;
    if (out_size >= 345600) {
        float* og = out + 57600;
        #pragma unroll
        for (int l = 0; l < 5; l++) og[o * 5 + l] = grp[l];
    }
}

// ---------------- launch ----------------
extern "C" void kernel_launch(void* const* d_in, const int* in_sizes, int n_in,
                              void* d_out, int out_size) {
    const float* l0 = (const float*)d_in[0];
    const float* l1 = (const float*)d_in[1];
    const float* l2 = (const float*)d_in[2];
    const float* l3 = (const float*)d_in[3];
    const float* l4 = (const float*)d_in[4];

    k_init<<<(TOT_CH * 6 + 255) / 256, 256>>>();
    k_minmaxAll<<<2816, 256>>>(l0, l1, l2, l3, l4);
    k_histAll<<<2816, 256>>>(l0, l1, l2, l3, l4);
    k_tables<<<(TOT_CH + 127) / 128, 128>>>();
    k_procfill<<<(306900 + 255) / 256, 256>>>();
    k_scatter<<<256, 256>>>();
    k_procstats<<<1201, 256>>>();
    k_resize<<<dim3(225, 5), 256>>>();
    k_final<<<225, 256>>>((float*)d_out, out_size);
}